// round 7
// baseline (speedup 1.0000x reference)
#include <cuda_runtime.h>
#include <stdint.h>

#define IN_F   2048
#define OUT_F  2048
#define TOPK   1024
#define M_FIX  16384

#define BM 256
#define BN 128
#define BK 32
#define NSTAGES 4
#define NT (IN_F / BK)              // 64
#define STAGE_BYTES 49152           // A 32KB + B 16KB
#define B_OFF 32768
#define DSMEM (NSTAGES * STAGE_BYTES + 1024)

// Scratch: masked W (tf32-RNA, [out][in]) and tf32-RNA-rounded activations.
__device__ float g_wm[(size_t)OUT_F * IN_F];
__device__ float g_a [(size_t)M_FIX * IN_F];

__device__ __forceinline__ float tf32_rna(float f) {
    unsigned r;
    asm("cvt.rna.tf32.f32 %0, %1;" : "=r"(r) : "f"(f));
    return __uint_as_float(r);
}
__device__ __forceinline__ uint32_t smem_u32(const void* p) {
    return (uint32_t)__cvta_generic_to_shared(p);
}
__device__ __forceinline__ void cp16cg(uint32_t dst, const void* src) {
    asm volatile("cp.async.cg.shared.global [%0], [%1], 16;\n" :: "r"(dst), "l"(src));
}
__device__ __forceinline__ void ldm_x4(uint32_t (&r)[4], uint32_t addr) {
    asm volatile("ldmatrix.sync.aligned.m8n8.x4.shared.b16 {%0,%1,%2,%3}, [%4];"
                 : "=r"(r[0]), "=r"(r[1]), "=r"(r[2]), "=r"(r[3]) : "r"(addr));
}
__device__ __forceinline__ void mma_tf32(float c[4], const uint32_t a[4], const uint32_t b[2]) {
    asm volatile(
        "mma.sync.aligned.m16n8k8.row.col.f32.tf32.tf32.f32 "
        "{%0,%1,%2,%3}, {%4,%5,%6,%7}, {%8,%9}, {%0,%1,%2,%3};\n"
        : "+f"(c[0]), "+f"(c[1]), "+f"(c[2]), "+f"(c[3])
        : "r"(a[0]), "r"(a[1]), "r"(a[2]), "r"(a[3]), "r"(b[0]), "r"(b[1]));
}

// ---------------------------------------------------------------------------
// Kernel 1: per-row exact top-k mask (radix select on |w| bits, ties kept
// lowest-index-first per jax.lax.top_k). Parallel suffix/prefix scans.
// Writes masked W row-major, tf32-RNA rounded, into g_wm.
// ---------------------------------------------------------------------------
__global__ void mask_kernel(const float* __restrict__ W) {
    __shared__ unsigned s_bits[IN_F];
    __shared__ int s_hist[256];
    __shared__ int s_tmp[256];
    __shared__ int s_sel[2];

    const int row = blockIdx.x;
    const int tid = threadIdx.x;
    const float* wrow = W + (size_t)row * IN_F;

    for (int i = tid; i < IN_F; i += 256)
        s_bits[i] = __float_as_uint(wrow[i]) & 0x7fffffffu;
    __syncthreads();

    unsigned prefix = 0;
    int k = TOPK;
    #pragma unroll
    for (int pass = 0; pass < 4; ++pass) {
        const int shift = 24 - 8 * pass;
        s_hist[tid] = 0;
        __syncthreads();
        const unsigned pm = (pass == 0) ? 0u : (0xffffffffu << (shift + 8));
        for (int i = tid; i < IN_F; i += 256) {
            unsigned b = s_bits[i];
            if ((b & pm) == prefix)
                atomicAdd(&s_hist[(b >> shift) & 0xffu], 1);
        }
        __syncthreads();
        // Parallel inclusive SUFFIX scan of s_hist.
        int v = s_hist[tid];
        #pragma unroll
        for (int off = 1; off < 256; off <<= 1) {
            s_tmp[tid] = v;
            __syncthreads();
            if (tid + off < 256) v += s_tmp[tid + off];
            __syncthreads();
        }
        s_tmp[tid] = v;                 // s_tmp[d] = count of bins >= d
        __syncthreads();
        const int suf1 = (tid < 255) ? s_tmp[tid + 1] : 0;
        if (v >= k && suf1 < k) {       // exactly one d satisfies this
            s_sel[0] = tid;
            s_sel[1] = k - suf1;
        }
        __syncthreads();
        prefix |= ((unsigned)s_sel[0]) << shift;
        k = s_sel[1];
        __syncthreads();
    }
    const unsigned t = prefix;          // k-th largest |w| bit pattern
    const int kfin = k;                 // # of ==t to keep (lowest index first)

    // Count ==t per contiguous 8-col chunk, parallel inclusive prefix scan.
    const int CH = IN_F / 256;
    const int base = tid * CH;
    int cnt = 0;
    #pragma unroll
    for (int j = 0; j < CH; ++j)
        if (s_bits[base + j] == t) cnt++;
    int v2 = cnt;
    #pragma unroll
    for (int off = 1; off < 256; off <<= 1) {
        s_tmp[tid] = v2;
        __syncthreads();
        if (tid >= off) v2 += s_tmp[tid - off];
        __syncthreads();
    }
    int eq_before = v2 - cnt;           // exclusive prefix

    #pragma unroll
    for (int j = 0; j < CH; ++j) {
        const int c = base + j;
        const unsigned b = s_bits[c];
        float v = 0.0f;
        if (b > t) {
            v = tf32_rna(wrow[c]);
        } else if (b == t) {
            if (eq_before < kfin) v = tf32_rna(wrow[c]);
            eq_before++;
        }
        g_wm[(size_t)row * IN_F + c] = v;
    }
}

// ---------------------------------------------------------------------------
// Kernel 2: round x to tf32 (RNA) once into g_a.
// ---------------------------------------------------------------------------
__global__ void cvt_a_kernel(const float4* __restrict__ x, int n4) {
    int i = blockIdx.x * blockDim.x + threadIdx.x;
    if (i < n4) {
        float4 v = x[i];
        v.x = tf32_rna(v.x);
        v.y = tf32_rna(v.y);
        v.z = tf32_rna(v.z);
        v.w = tf32_rna(v.w);
        reinterpret_cast<float4*>(g_a)[i] = v;
    }
}

// ---------------------------------------------------------------------------
// Kernel 3: tf32 mma.sync GEMM.  C[m][n] = sum_k A[m][k]*Wm[n][k] + bias[n]
// 256x128 CTA tile, BK=32, 256 threads, 4x2 warp grid of 64x64 warp tiles
// (minimal smem fragment traffic: 69% of tensor time), ldmatrix.x4 from
// XOR-swizzled smem, 4-stage cp.async ring, single __syncthreads per k-iter.
// Operands pre-rounded -> pure ldmatrix+mma inner loop.
// ---------------------------------------------------------------------------
__global__ __launch_bounds__(256, 1)
void gemm_kernel(const float* __restrict__ bias, float* __restrict__ C) {
    extern __shared__ char dsm[];
    __shared__ float s_bias[BN];

    const int tid  = threadIdx.x;
    const int lane = tid & 31;
    const int wid  = tid >> 5;
    const int wm   = wid >> 1;           // 0..3  (64 rows each)
    const int wn   = wid & 1;            // 0..1  (64 cols each)
    const int m0 = blockIdx.y * BM;
    const int n0 = blockIdx.x * BN;

    const uint32_t base = (smem_u32(dsm) + 1023) & ~1023u;
    if (tid < BN) s_bias[tid] = bias[n0 + tid];

    // ldmatrix lane addressing: row-in-16 = lane&15, chunk-sel = lane>>4,
    // swizzle xor = (lane&7)<<4 (row-tile bases are multiples of 8).
    const int lrow = lane & 15;
    const int lsel = lane >> 4;
    const uint32_t lxor = (uint32_t)((lane & 7) << 4);

    auto issue = [&](int kt, int st) {
        const uint32_t sa = base + st * STAGE_BYTES;
        const int k0 = kt * BK;
        #pragma unroll
        for (int i = 0; i < 8; ++i) {            // A: 256 rows x 128B
            const int id = i * 256 + tid;
            const int m = id >> 3, j = id & 7;
            cp16cg(sa + m * 128 + (((uint32_t)(j << 4)) ^ ((uint32_t)((m & 7) << 4))),
                   g_a + (size_t)(m0 + m) * IN_F + k0 + j * 4);
        }
        #pragma unroll
        for (int i = 0; i < 4; ++i) {            // B: 128 rows x 128B
            const int id = i * 256 + tid;
            const int n = id >> 3, j = id & 7;
            cp16cg(sa + B_OFF + n * 128 + (((uint32_t)(j << 4)) ^ ((uint32_t)((n & 7) << 4))),
                   g_wm + (size_t)(n0 + n) * IN_F + k0 + j * 4);
        }
        asm volatile("cp.async.commit_group;\n" ::);
    };

    float acc[4][8][4] = {};

    issue(0, 0);
    issue(1, 1);
    issue(2, 2);

    int st = 0;
    for (int kt = 0; kt < NT; ++kt) {
        if (kt < NT - 3)
            asm volatile("cp.async.wait_group 2;\n" ::);
        else
            asm volatile("cp.async.wait_group 0;\n" ::);
        __syncthreads();

        if (kt + 3 < NT) {
            int st3 = st + 3;
            if (st3 >= NSTAGES) st3 -= NSTAGES;
            issue(kt + 3, st3);
        }

        const uint32_t sa = base + st * STAGE_BYTES;
        const uint32_t sb = sa + B_OFF;

        #pragma unroll
        for (int kk = 0; kk < 4; ++kk) {         // 4 k-chunks of 8 in BK=32
            const uint32_t csel = (((uint32_t)((kk * 2 + lsel) << 4)) ^ lxor);
            uint32_t a[4][4];
            uint32_t b[8][2];
            #pragma unroll
            for (int np = 0; np < 4; ++np) {
                uint32_t r[4];
                ldm_x4(r, sb + (uint32_t)((wn * 64 + np * 16 + lrow) * 128) + csel);
                b[2 * np][0] = r[0]; b[2 * np + 1][0] = r[1];
                b[2 * np][1] = r[2]; b[2 * np + 1][1] = r[3];
            }
            #pragma unroll
            for (int mt = 0; mt < 4; ++mt)
                ldm_x4(a[mt], sa + (uint32_t)((wm * 64 + mt * 16 + lrow) * 128) + csel);
            #pragma unroll
            for (int mt = 0; mt < 4; ++mt)
                #pragma unroll
                for (int nt = 0; nt < 8; ++nt)
                    mma_tf32(acc[mt][nt], a[mt], b[nt]);
        }
        ++st;
        if (st == NSTAGES) st = 0;
    }

    // Epilogue: bias add, float2 stores.
    const int g = lane >> 2;
    const int t = lane & 3;
    #pragma unroll
    for (int mt = 0; mt < 4; ++mt) {
        const int r0 = m0 + wm * 64 + mt * 16 + g;
        #pragma unroll
        for (int nt = 0; nt < 8; ++nt) {
            const int cl = wn * 64 + nt * 8 + t * 2;   // local col in [0,128)
            const float bx = s_bias[cl], by = s_bias[cl + 1];
            float2 o0, o1;
            o0.x = acc[mt][nt][0] + bx;
            o0.y = acc[mt][nt][1] + by;
            o1.x = acc[mt][nt][2] + bx;
            o1.y = acc[mt][nt][3] + by;
            *reinterpret_cast<float2*>(C + (size_t)r0 * OUT_F + n0 + cl) = o0;
            *reinterpret_cast<float2*>(C + (size_t)(r0 + 8) * OUT_F + n0 + cl) = o1;
        }
    }
}

// ---------------------------------------------------------------------------
extern "C" void kernel_launch(void* const* d_in, const int* in_sizes, int n_in,
                              void* d_out, int out_size) {
    const float* x    = (const float*)d_in[0];   // [M, 2048]
    const float* W    = (const float*)d_in[1];   // [2048, 2048]
    const float* bias = (const float*)d_in[2];   // [2048]
    float* out = (float*)d_out;

    const int M = in_sizes[0] / IN_F;            // 16384

    cudaFuncSetAttribute(gemm_kernel,
                         cudaFuncAttributeMaxDynamicSharedMemorySize, DSMEM);

    mask_kernel<<<OUT_F, 256>>>(W);
    const int n4 = M * IN_F / 4;
    cvt_a_kernel<<<(n4 + 255) / 256, 256>>>((const float4*)x, n4);
    dim3 grid(OUT_F / BN, M / BM);               // (16, 64)
    gemm_kernel<<<grid, 256, DSMEM>>>(bias, out);
}

// round 8
// speedup vs baseline: 1.0591x; 1.0591x over previous
#include <cuda_runtime.h>
#include <stdint.h>

#define IN_F   2048
#define OUT_F  2048
#define TOPK   1024
#define M_FIX  16384

#define BM 128
#define BN 128
#define BK 32
#define NSTAGES 3
#define NT (IN_F / BK)              // 64
#define STAGE_BYTES 32768           // A 16KB + B 16KB
#define B_OFF 16384
#define DSMEM (NSTAGES * STAGE_BYTES + 1024)

// Scratch: masked W (tf32-RNA, [out][in]) and tf32-RNA-rounded activations.
__device__ float g_wm[(size_t)OUT_F * IN_F];
__device__ float g_a [(size_t)M_FIX * IN_F];

__device__ __forceinline__ float tf32_rna(float f) {
    unsigned r;
    asm("cvt.rna.tf32.f32 %0, %1;" : "=r"(r) : "f"(f));
    return __uint_as_float(r);
}
__device__ __forceinline__ uint32_t smem_u32(const void* p) {
    return (uint32_t)__cvta_generic_to_shared(p);
}
__device__ __forceinline__ void cp16cg(uint32_t dst, const void* src) {
    asm volatile("cp.async.cg.shared.global [%0], [%1], 16;\n" :: "r"(dst), "l"(src));
}
__device__ __forceinline__ void ldm_x4(uint32_t (&r)[4], uint32_t addr) {
    asm volatile("ldmatrix.sync.aligned.m8n8.x4.shared.b16 {%0,%1,%2,%3}, [%4];"
                 : "=r"(r[0]), "=r"(r[1]), "=r"(r[2]), "=r"(r[3]) : "r"(addr));
}
__device__ __forceinline__ void mma_tf32(float c[4], const uint32_t a[4], const uint32_t b[2]) {
    asm volatile(
        "mma.sync.aligned.m16n8k8.row.col.f32.tf32.tf32.f32 "
        "{%0,%1,%2,%3}, {%4,%5,%6,%7}, {%8,%9}, {%0,%1,%2,%3};\n"
        : "+f"(c[0]), "+f"(c[1]), "+f"(c[2]), "+f"(c[3])
        : "r"(a[0]), "r"(a[1]), "r"(a[2]), "r"(a[3]), "r"(b[0]), "r"(b[1]));
}

// ---------------------------------------------------------------------------
// Kernel 1 (fused prep):
//   blocks [0, 2048): per-row exact top-k mask (radix select on |w| bits,
//     ties lowest-index-first per jax.lax.top_k), masked W -> g_wm (tf32 RNA).
//   blocks [2048, 4096): round x to tf32 RNA into g_a (4096 float4 each).
// Both jobs are independent and bandwidth-starved alone; co-scheduling
// overlaps their memory streams.
// ---------------------------------------------------------------------------
__global__ void prep_kernel(const float* __restrict__ W,
                            const float4* __restrict__ x) {
    __shared__ unsigned s_bits[IN_F];
    __shared__ int s_hist[256];
    __shared__ int s_tmp[256];
    __shared__ int s_sel[2];

    const int tid = threadIdx.x;

    if (blockIdx.x >= OUT_F) {
        // ---- cvt job: 4096 float4 per block, 16 per thread ----
        const size_t base = (size_t)(blockIdx.x - OUT_F) * 4096 + tid;
        float4* dst = reinterpret_cast<float4*>(g_a);
        #pragma unroll
        for (int i = 0; i < 16; ++i) {
            const size_t idx = base + (size_t)i * 256;
            float4 v = x[idx];
            v.x = tf32_rna(v.x);
            v.y = tf32_rna(v.y);
            v.z = tf32_rna(v.z);
            v.w = tf32_rna(v.w);
            dst[idx] = v;
        }
        return;
    }

    // ---- mask job ----
    const int row = blockIdx.x;
    const float* wrow = W + (size_t)row * IN_F;

    for (int i = tid; i < IN_F; i += 256)
        s_bits[i] = __float_as_uint(wrow[i]) & 0x7fffffffu;
    __syncthreads();

    unsigned prefix = 0;
    int k = TOPK;
    #pragma unroll
    for (int pass = 0; pass < 4; ++pass) {
        const int shift = 24 - 8 * pass;
        s_hist[tid] = 0;
        __syncthreads();
        const unsigned pm = (pass == 0) ? 0u : (0xffffffffu << (shift + 8));
        for (int i = tid; i < IN_F; i += 256) {
            unsigned b = s_bits[i];
            if ((b & pm) == prefix)
                atomicAdd(&s_hist[(b >> shift) & 0xffu], 1);
        }
        __syncthreads();
        // Parallel inclusive SUFFIX scan of s_hist.
        int v = s_hist[tid];
        #pragma unroll
        for (int off = 1; off < 256; off <<= 1) {
            s_tmp[tid] = v;
            __syncthreads();
            if (tid + off < 256) v += s_tmp[tid + off];
            __syncthreads();
        }
        s_tmp[tid] = v;                 // s_tmp[d] = count of bins >= d
        __syncthreads();
        const int suf1 = (tid < 255) ? s_tmp[tid + 1] : 0;
        if (v >= k && suf1 < k) {       // exactly one d satisfies this
            s_sel[0] = tid;
            s_sel[1] = k - suf1;
        }
        __syncthreads();
        prefix |= ((unsigned)s_sel[0]) << shift;
        k = s_sel[1];
        __syncthreads();
    }
    const unsigned t = prefix;          // k-th largest |w| bit pattern
    const int kfin = k;                 // # of ==t to keep (lowest index first)

    // Count ==t per contiguous 8-col chunk, parallel inclusive prefix scan.
    const int CH = IN_F / 256;
    const int base = tid * CH;
    int cnt = 0;
    #pragma unroll
    for (int j = 0; j < CH; ++j)
        if (s_bits[base + j] == t) cnt++;
    int v2 = cnt;
    #pragma unroll
    for (int off = 1; off < 256; off <<= 1) {
        s_tmp[tid] = v2;
        __syncthreads();
        if (tid >= off) v2 += s_tmp[tid - off];
        __syncthreads();
    }
    int eq_before = v2 - cnt;           // exclusive prefix

    #pragma unroll
    for (int j = 0; j < CH; ++j) {
        const int c = base + j;
        const unsigned b = s_bits[c];
        float v = 0.0f;
        if (b > t) {
            v = tf32_rna(wrow[c]);
        } else if (b == t) {
            if (eq_before < kfin) v = tf32_rna(wrow[c]);
            eq_before++;
        }
        g_wm[(size_t)row * IN_F + c] = v;
    }
}

// ---------------------------------------------------------------------------
// Kernel 2: tf32 mma.sync GEMM.  C[m][n] = sum_k A[m][k]*Wm[n][k] + bias[n]
// 128x128 tile, BK=32, 256 threads, 2x4 warp grid, 64x32 warp tiles,
// ldmatrix.x4 from XOR-swizzled smem, 3-stage cp.async ring, single
// __syncthreads per k-iter, pure ldmatrix+mma inner loop, 2 CTAs/SM.
// (Best measured GEMM config: ~712us — kept byte-identical to round 6.)
// ---------------------------------------------------------------------------
__global__ __launch_bounds__(256, 2)
void gemm_kernel(const float* __restrict__ bias, float* __restrict__ C) {
    extern __shared__ char dsm[];
    __shared__ float s_bias[BN];

    const int tid  = threadIdx.x;
    const int lane = tid & 31;
    const int wid  = tid >> 5;
    const int wm   = wid >> 2;           // 0..1  (64 rows each)
    const int wn   = wid & 3;            // 0..3  (32 cols each)
    const int m0 = blockIdx.y * BM;
    const int n0 = blockIdx.x * BN;

    const uint32_t base = (smem_u32(dsm) + 1023) & ~1023u;
    if (tid < BN) s_bias[tid] = bias[n0 + tid];

    const int lrow = lane & 15;
    const int lsel = lane >> 4;
    const uint32_t lxor = (uint32_t)((lane & 7) << 4);

    auto issue = [&](int kt, int st) {
        const uint32_t sa = base + st * STAGE_BYTES;
        const int k0 = kt * BK;
        #pragma unroll
        for (int i = 0; i < 4; ++i) {            // A: 128 rows x 128B
            const int id = i * 256 + tid;
            const int m = id >> 3, j = id & 7;
            cp16cg(sa + m * 128 + (((uint32_t)(j << 4)) ^ ((uint32_t)((m & 7) << 4))),
                   g_a + (size_t)(m0 + m) * IN_F + k0 + j * 4);
        }
        #pragma unroll
        for (int i = 0; i < 4; ++i) {            // B: 128 rows x 128B
            const int id = i * 256 + tid;
            const int n = id >> 3, j = id & 7;
            cp16cg(sa + B_OFF + n * 128 + (((uint32_t)(j << 4)) ^ ((uint32_t)((n & 7) << 4))),
                   g_wm + (size_t)(n0 + n) * IN_F + k0 + j * 4);
        }
        asm volatile("cp.async.commit_group;\n" ::);
    };

    float acc[4][4][4] = {};

    issue(0, 0);
    issue(1, 1);

    int st = 0;
    for (int kt = 0; kt < NT; ++kt) {
        if (kt < NT - 2)
            asm volatile("cp.async.wait_group 1;\n" ::);
        else
            asm volatile("cp.async.wait_group 0;\n" ::);
        __syncthreads();

        if (kt + 2 < NT) {
            int st2 = st + 2;
            if (st2 >= NSTAGES) st2 -= NSTAGES;
            issue(kt + 2, st2);
        }

        const uint32_t sa = base + st * STAGE_BYTES;
        const uint32_t sb = sa + B_OFF;

        #pragma unroll
        for (int kk = 0; kk < 4; ++kk) {         // 4 k-chunks of 8 in BK=32
            const uint32_t csel = (((uint32_t)((kk * 2 + lsel) << 4)) ^ lxor);
            uint32_t a[4][4];
            uint32_t b[4][2];
            #pragma unroll
            for (int np = 0; np < 2; ++np) {
                uint32_t r[4];
                ldm_x4(r, sb + (uint32_t)((wn * 32 + np * 16 + lrow) * 128) + csel);
                b[2 * np][0] = r[0]; b[2 * np + 1][0] = r[1];
                b[2 * np][1] = r[2]; b[2 * np + 1][1] = r[3];
            }
            #pragma unroll
            for (int mt = 0; mt < 4; ++mt)
                ldm_x4(a[mt], sa + (uint32_t)((wm * 64 + mt * 16 + lrow) * 128) + csel);
            #pragma unroll
            for (int mt = 0; mt < 4; ++mt)
                #pragma unroll
                for (int nt = 0; nt < 4; ++nt)
                    mma_tf32(acc[mt][nt], a[mt], b[nt]);
        }
        ++st;
        if (st == NSTAGES) st = 0;
    }

    // Epilogue: bias add, float2 stores.
    const int g = lane >> 2;
    const int t = lane & 3;
    #pragma unroll
    for (int mt = 0; mt < 4; ++mt) {
        const int r0 = m0 + wm * 64 + mt * 16 + g;
        #pragma unroll
        for (int nt = 0; nt < 4; ++nt) {
            const int cl = wn * 32 + nt * 8 + t * 2;   // local col in [0,128)
            const float bx = s_bias[cl], by = s_bias[cl + 1];
            float2 o0, o1;
            o0.x = acc[mt][nt][0] + bx;
            o0.y = acc[mt][nt][1] + by;
            o1.x = acc[mt][nt][2] + bx;
            o1.y = acc[mt][nt][3] + by;
            *reinterpret_cast<float2*>(C + (size_t)r0 * OUT_F + n0 + cl) = o0;
            *reinterpret_cast<float2*>(C + (size_t)(r0 + 8) * OUT_F + n0 + cl) = o1;
        }
    }
}

// ---------------------------------------------------------------------------
extern "C" void kernel_launch(void* const* d_in, const int* in_sizes, int n_in,
                              void* d_out, int out_size) {
    const float* x    = (const float*)d_in[0];   // [M, 2048]
    const float* W    = (const float*)d_in[1];   // [2048, 2048]
    const float* bias = (const float*)d_in[2];   // [2048]
    float* out = (float*)d_out;

    const int M = in_sizes[0] / IN_F;            // 16384

    cudaFuncSetAttribute(gemm_kernel,
                         cudaFuncAttributeMaxDynamicSharedMemorySize, DSMEM);

    // Fused prep: 2048 mask blocks + 2048 cvt blocks (M*IN_F/4/4096 = 2048).
    const int cvt_blocks = (M * (IN_F / 4)) / 4096;
    prep_kernel<<<OUT_F + cvt_blocks, 256>>>(W, (const float4*)x);

    dim3 grid(OUT_F / BN, M / BM);               // (16, 128)
    gemm_kernel<<<grid, 256, DSMEM>>>(bias, out);
}

// round 9
// speedup vs baseline: 2.2768x; 2.1497x over previous
#include <cuda_runtime.h>
#include <cuda_fp16.h>
#include <stdint.h>

#define IN_F   2048
#define OUT_F  2048
#define TOPK   1024
#define M_FIX  16384

#define BM 128
#define BN 128
#define BK 64
#define NSTAGES 3
#define NT (IN_F / BK)              // 32
#define STAGE_BYTES 32768           // A 16KB + B 16KB (fp16)
#define B_OFF 16384
#define DSMEM (NSTAGES * STAGE_BYTES + 1024)

// Scratch: masked W (fp16, [out][in]) and fp16 activations.
__device__ __half g_wh[(size_t)OUT_F * IN_F];
__device__ __half g_ah[(size_t)M_FIX * IN_F];

__device__ __forceinline__ uint32_t smem_u32(const void* p) {
    return (uint32_t)__cvta_generic_to_shared(p);
}
__device__ __forceinline__ void cp16cg(uint32_t dst, const void* src) {
    asm volatile("cp.async.cg.shared.global [%0], [%1], 16;\n" :: "r"(dst), "l"(src));
}
__device__ __forceinline__ void ldm_x4(uint32_t (&r)[4], uint32_t addr) {
    asm volatile("ldmatrix.sync.aligned.m8n8.x4.shared.b16 {%0,%1,%2,%3}, [%4];"
                 : "=r"(r[0]), "=r"(r[1]), "=r"(r[2]), "=r"(r[3]) : "r"(addr));
}
__device__ __forceinline__ void mma_f16(float c[4], const uint32_t a[4], const uint32_t b[2]) {
    asm volatile(
        "mma.sync.aligned.m16n8k16.row.col.f32.f16.f16.f32 "
        "{%0,%1,%2,%3}, {%4,%5,%6,%7}, {%8,%9}, {%0,%1,%2,%3};\n"
        : "+f"(c[0]), "+f"(c[1]), "+f"(c[2]), "+f"(c[3])
        : "r"(a[0]), "r"(a[1]), "r"(a[2]), "r"(a[3]), "r"(b[0]), "r"(b[1]));
}

// ---------------------------------------------------------------------------
// Kernel 1 (fused prep):
//   blocks [0, 2048): per-row exact top-k mask (radix select on |w| bits,
//     ties lowest-index-first per jax.lax.top_k) -> g_wh as fp16 (RN).
//     NOTE: kept weights are the largest 1024 of 2048 (smallest ~0.011),
//     far above fp16's normal floor — no subnormal error exposure.
//   blocks [2048, 4096): convert x to fp16 (RN) into g_ah.
// ---------------------------------------------------------------------------
__global__ void prep_kernel(const float* __restrict__ W,
                            const float4* __restrict__ x) {
    __shared__ unsigned s_bits[IN_F];
    __shared__ int s_hist[256];
    __shared__ int s_tmp[256];
    __shared__ int s_sel[2];

    const int tid = threadIdx.x;

    if (blockIdx.x >= OUT_F) {
        // ---- cvt job: 4096 float4 per block, 16 per thread ----
        const size_t base = (size_t)(blockIdx.x - OUT_F) * 4096 + tid;
        #pragma unroll
        for (int i = 0; i < 16; ++i) {
            const size_t idx = base + (size_t)i * 256;
            float4 v = x[idx];
            __half2 h0 = __floats2half2_rn(v.x, v.y);
            __half2 h1 = __floats2half2_rn(v.z, v.w);
            uint2 o;
            o.x = *reinterpret_cast<uint32_t*>(&h0);
            o.y = *reinterpret_cast<uint32_t*>(&h1);
            *reinterpret_cast<uint2*>(g_ah + idx * 4) = o;
        }
        return;
    }

    // ---- mask job ----
    const int row = blockIdx.x;
    const float* wrow = W + (size_t)row * IN_F;

    for (int i = tid; i < IN_F; i += 256)
        s_bits[i] = __float_as_uint(wrow[i]) & 0x7fffffffu;
    __syncthreads();

    unsigned prefix = 0;
    int k = TOPK;
    #pragma unroll
    for (int pass = 0; pass < 4; ++pass) {
        const int shift = 24 - 8 * pass;
        s_hist[tid] = 0;
        __syncthreads();
        const unsigned pm = (pass == 0) ? 0u : (0xffffffffu << (shift + 8));
        for (int i = tid; i < IN_F; i += 256) {
            unsigned b = s_bits[i];
            if ((b & pm) == prefix)
                atomicAdd(&s_hist[(b >> shift) & 0xffu], 1);
        }
        __syncthreads();
        // Parallel inclusive SUFFIX scan of s_hist.
        int v = s_hist[tid];
        #pragma unroll
        for (int off = 1; off < 256; off <<= 1) {
            s_tmp[tid] = v;
            __syncthreads();
            if (tid + off < 256) v += s_tmp[tid + off];
            __syncthreads();
        }
        s_tmp[tid] = v;                 // s_tmp[d] = count of bins >= d
        __syncthreads();
        const int suf1 = (tid < 255) ? s_tmp[tid + 1] : 0;
        if (v >= k && suf1 < k) {       // exactly one d satisfies this
            s_sel[0] = tid;
            s_sel[1] = k - suf1;
        }
        __syncthreads();
        prefix |= ((unsigned)s_sel[0]) << shift;
        k = s_sel[1];
        __syncthreads();
    }
    const unsigned t = prefix;          // k-th largest |w| bit pattern
    const int kfin = k;                 // # of ==t to keep (lowest index first)

    // Count ==t per contiguous 8-col chunk, parallel inclusive prefix scan.
    const int CH = IN_F / 256;
    const int base = tid * CH;
    int cnt = 0;
    #pragma unroll
    for (int j = 0; j < CH; ++j)
        if (s_bits[base + j] == t) cnt++;
    int v2 = cnt;
    #pragma unroll
    for (int off = 1; off < 256; off <<= 1) {
        s_tmp[tid] = v2;
        __syncthreads();
        if (tid >= off) v2 += s_tmp[tid - off];
        __syncthreads();
    }
    int eq_before = v2 - cnt;           // exclusive prefix

    #pragma unroll
    for (int j = 0; j < CH; ++j) {
        const int c = base + j;
        const unsigned b = s_bits[c];
        float v = 0.0f;
        if (b > t) {
            v = wrow[c];
        } else if (b == t) {
            if (eq_before < kfin) v = wrow[c];
            eq_before++;
        }
        g_wh[(size_t)row * IN_F + c] = __float2half_rn(v);
    }
}

// ---------------------------------------------------------------------------
// Kernel 2: fp16 mma.sync GEMM (f32 accumulate).
//   C[m][n] = sum_k A[m][k]*Wm[n][k] + bias[n]
// 128x128 tile, BK=64, 256 threads, 2x4 warp grid, 64x32 warp tiles,
// mma.m16n8k16, ldmatrix.x4 from XOR-swizzled smem (128B rows = 64 halves),
// 3-stage cp.async ring, single __syncthreads per k-iter, 2 CTAs/SM.
// ---------------------------------------------------------------------------
__global__ __launch_bounds__(256, 2)
void gemm_kernel(const float* __restrict__ bias, float* __restrict__ C) {
    extern __shared__ char dsm[];
    __shared__ float s_bias[BN];

    const int tid  = threadIdx.x;
    const int lane = tid & 31;
    const int wid  = tid >> 5;
    const int wm   = wid >> 2;           // 0..1  (64 rows each)
    const int wn   = wid & 3;            // 0..3  (32 cols each)
    const int m0 = blockIdx.y * BM;
    const int n0 = blockIdx.x * BN;

    const uint32_t base = (smem_u32(dsm) + 1023) & ~1023u;
    if (tid < BN) s_bias[tid] = bias[n0 + tid];

    // A ldmatrix lanes: row-in-16 = lane&15, k16-half-sel = lane>>4.
    const int lrow = lane & 15;
    const int lsel = lane >> 4;
    const uint32_t lxor_a = (uint32_t)((lane & 7) << 4);
    // B ldmatrix lanes: n-row = (lane&7) + 8*(lane>>4), k16-half = (lane>>3)&1.
    const int brow = (lane & 7) + ((lane >> 4) << 3);
    const int bsel = (lane >> 3) & 1;
    const uint32_t lxor_b = (uint32_t)((lane & 7) << 4);

    auto issue = [&](int kt, int st) {
        const uint32_t sa = base + st * STAGE_BYTES;
        const int k0 = kt * BK;
        #pragma unroll
        for (int i = 0; i < 4; ++i) {            // A: 128 rows x 128B (64 halves)
            const int id = i * 256 + tid;
            const int m = id >> 3, j = id & 7;
            cp16cg(sa + m * 128 + (((uint32_t)(j << 4)) ^ ((uint32_t)((m & 7) << 4))),
                   g_ah + (size_t)(m0 + m) * IN_F + k0 + j * 8);
        }
        #pragma unroll
        for (int i = 0; i < 4; ++i) {            // B: 128 rows x 128B
            const int id = i * 256 + tid;
            const int n = id >> 3, j = id & 7;
            cp16cg(sa + B_OFF + n * 128 + (((uint32_t)(j << 4)) ^ ((uint32_t)((n & 7) << 4))),
                   g_wh + (size_t)(n0 + n) * IN_F + k0 + j * 8);
        }
        asm volatile("cp.async.commit_group;\n" ::);
    };

    float acc[4][4][4] = {};

    issue(0, 0);
    issue(1, 1);

    int st = 0;
    for (int kt = 0; kt < NT; ++kt) {
        if (kt < NT - 2)
            asm volatile("cp.async.wait_group 1;\n" ::);
        else
            asm volatile("cp.async.wait_group 0;\n" ::);
        __syncthreads();

        if (kt + 2 < NT) {
            int st2 = st + 2;
            if (st2 >= NSTAGES) st2 -= NSTAGES;
            issue(kt + 2, st2);
        }

        const uint32_t sa = base + st * STAGE_BYTES;
        const uint32_t sb = sa + B_OFF;

        #pragma unroll
        for (int kk = 0; kk < 4; ++kk) {         // 4 k16 chunks in BK=64
            // A fragments: granule = 2kk + lsel (16B = 8 halves).
            const uint32_t csel_a = (((uint32_t)((kk * 2 + lsel) << 4)) ^ lxor_a);
            // B fragments: granule = 2kk + bsel.
            const uint32_t csel_b = (((uint32_t)((kk * 2 + bsel) << 4)) ^ lxor_b);
            uint32_t a[4][4];
            uint32_t b[4][2];
            #pragma unroll
            for (int np = 0; np < 2; ++np) {
                uint32_t r[4];
                ldm_x4(r, sb + (uint32_t)((wn * 32 + np * 16 + brow) * 128) + csel_b);
                b[2 * np][0] = r[0]; b[2 * np][1] = r[1];
                b[2 * np + 1][0] = r[2]; b[2 * np + 1][1] = r[3];
            }
            #pragma unroll
            for (int mt = 0; mt < 4; ++mt)
                ldm_x4(a[mt], sa + (uint32_t)((wm * 64 + mt * 16 + lrow) * 128) + csel_a);
            #pragma unroll
            for (int mt = 0; mt < 4; ++mt)
                #pragma unroll
                for (int nt = 0; nt < 4; ++nt)
                    mma_f16(acc[mt][nt], a[mt], b[nt]);
        }
        ++st;
        if (st == NSTAGES) st = 0;
    }

    // Epilogue: bias add, float2 stores.
    const int g = lane >> 2;
    const int t = lane & 3;
    #pragma unroll
    for (int mt = 0; mt < 4; ++mt) {
        const int r0 = m0 + wm * 64 + mt * 16 + g;
        #pragma unroll
        for (int nt = 0; nt < 4; ++nt) {
            const int cl = wn * 32 + nt * 8 + t * 2;   // local col in [0,128)
            const float bx = s_bias[cl], by = s_bias[cl + 1];
            float2 o0, o1;
            o0.x = acc[mt][nt][0] + bx;
            o0.y = acc[mt][nt][1] + by;
            o1.x = acc[mt][nt][2] + bx;
            o1.y = acc[mt][nt][3] + by;
            *reinterpret_cast<float2*>(C + (size_t)r0 * OUT_F + n0 + cl) = o0;
            *reinterpret_cast<float2*>(C + (size_t)(r0 + 8) * OUT_F + n0 + cl) = o1;
        }
    }
}

// ---------------------------------------------------------------------------
extern "C" void kernel_launch(void* const* d_in, const int* in_sizes, int n_in,
                              void* d_out, int out_size) {
    const float* x    = (const float*)d_in[0];   // [M, 2048]
    const float* W    = (const float*)d_in[1];   // [2048, 2048]
    const float* bias = (const float*)d_in[2];   // [2048]
    float* out = (float*)d_out;

    const int M = in_sizes[0] / IN_F;            // 16384

    cudaFuncSetAttribute(gemm_kernel,
                         cudaFuncAttributeMaxDynamicSharedMemorySize, DSMEM);

    // Fused prep: 2048 mask blocks + 2048 cvt blocks.
    const int cvt_blocks = (M * (IN_F / 4)) / 4096;
    prep_kernel<<<OUT_F + cvt_blocks, 256>>>(W, (const float4*)x);

    dim3 grid(OUT_F / BN, M / BM);               // (16, 128)
    gemm_kernel<<<grid, 256, DSMEM>>>(bias, out);
}